// round 1
// baseline (speedup 1.0000x reference)
#include <cuda_runtime.h>
#include <math.h>

// Problem constants: B=8, N=64, D=64, E=32
// Block = one (b, i_node) pair. Computes agg[b,i_node,:] fused with the
// edges@W_e GEMM + relu + mask/node weighting + reduction, then the 2-step GRU.

__global__ __launch_bounds__(256, 2) void mp_fused_kernel(
    const float* __restrict__ nodes,   // (8,64,64)
    const float* __restrict__ edges,   // (8,4096,32)
    const float* __restrict__ mask,    // (8,4096,1)
    const float* __restrict__ W_e,     // (32,4096)
    const float* __restrict__ b_e,     // (4096,)
    const float* __restrict__ Kmat,    // (64,192) gru_kernel
    const float* __restrict__ Rmat,    // (64,192) gru_rkernel
    const float* __restrict__ gbias,   // (2,192)
    float* __restrict__ out)           // (8,64,64)
{
    __shared__ float edges_sh[32][68];   // [k][j_node], padded for 16B-aligned LDS.128
    __shared__ float wt_sh[64][64];      // mask[e]*nodes[b][j_node][j]
    __shared__ float W_sh[32][132];      // [k][col within 128-chunk], padded
    __shared__ float xrow[64];           // nodes[b][i_node][:]
    __shared__ float aggs[64];
    __shared__ float xk1[192], h1[64], xk2[192], hk2[192];

    const int blk   = blockIdx.x;
    const int b     = blk >> 6;
    const int inode = blk & 63;
    const int t     = threadIdx.x;
    const int lane  = t & 31;
    const int warp  = t >> 5;

    // ---- load edges (64 edges x 32), transposed into shared ----
    {
        const float* ebase = edges + ((size_t)b * 4096 + (size_t)inode * 64) * 32;
        for (int i = t; i < 64 * 8; i += 256) {   // float4 granules
            int e = i >> 3;
            int q = i & 7;
            float4 v = *(const float4*)(ebase + e * 32 + q * 4);
            edges_sh[q * 4 + 0][e] = v.x;
            edges_sh[q * 4 + 1][e] = v.y;
            edges_sh[q * 4 + 2][e] = v.z;
            edges_sh[q * 4 + 3][e] = v.w;
        }
    }
    // ---- wt_sh = mask * nodes, xrow, zero agg ----
    {
        const float* nb = nodes + (size_t)b * 64 * 64;
        const float* mb = mask  + (size_t)b * 4096 + (size_t)inode * 64;
        for (int i = t; i < 64 * 16; i += 256) {  // float4 granules
            int r = i >> 4, q = i & 15;
            float m = mb[r];
            float4 v = *(const float4*)(nb + r * 64 + q * 4);
            float4 w; w.x = v.x * m; w.y = v.y * m; w.z = v.z * m; w.w = v.w * m;
            *(float4*)&wt_sh[r][q * 4] = w;
        }
        if (t < 16) {
            float4 v = *(const float4*)(nb + inode * 64 + t * 4);
            *(float4*)&xrow[t * 4] = v;
        }
        if (t < 64) aggs[t] = 0.0f;
    }

    // ---- prefetch first W chunk (32 x 128 floats) into registers ----
    float4 wpre[4];
    {
        #pragma unroll
        for (int u = 0; u < 4; u++) {
            int idx = t + u * 256;      // 0..1023
            int k   = idx >> 5;
            int c4  = idx & 31;
            wpre[u] = *(const float4*)(W_e + (size_t)k * 4096 + c4 * 4);
        }
    }
    __syncthreads();

    const int r0 = warp * 8;     // 8 rows (edges) per thread
    const int c0 = lane * 4;     // 4 cols per thread, 128 cols per iter

    for (int it = 0; it < 32; it++) {
        // commit prefetched W chunk to shared
        #pragma unroll
        for (int u = 0; u < 4; u++) {
            int idx = t + u * 256;
            int k = idx >> 5, c4 = idx & 31;
            *(float4*)&W_sh[k][c4 * 4] = wpre[u];
        }
        __syncthreads();
        // prefetch next chunk (hidden under FMA work)
        if (it + 1 < 32) {
            #pragma unroll
            for (int u = 0; u < 4; u++) {
                int idx = t + u * 256;
                int k = idx >> 5, c4 = idx & 31;
                wpre[u] = *(const float4*)(W_e + (size_t)k * 4096 + (size_t)(it + 1) * 128 + c4 * 4);
            }
        }

        float acc[8][4];
        #pragma unroll
        for (int i = 0; i < 8; i++)
            #pragma unroll
            for (int j = 0; j < 4; j++) acc[i][j] = 0.0f;

        #pragma unroll
        for (int k = 0; k < 32; k++) {
            float4 a0 = *(const float4*)&edges_sh[k][r0];
            float4 a1 = *(const float4*)&edges_sh[k][r0 + 4];
            float4 bv = *(const float4*)&W_sh[k][c0];
            float ar[8] = {a0.x, a0.y, a0.z, a0.w, a1.x, a1.y, a1.z, a1.w};
            float bc[4] = {bv.x, bv.y, bv.z, bv.w};
            #pragma unroll
            for (int i = 0; i < 8; i++)
                #pragma unroll
                for (int j = 0; j < 4; j++)
                    acc[i][j] = fmaf(ar[i], bc[j], acc[i][j]);
        }

        // epilogue: relu(pre + b_e) * (mask*nodes), reduce 8x4 -> scalar
        int cglob = it * 128 + c0;
        int jcol  = cglob & 63;           // j within i-group
        int ig    = cglob >> 6;           // global i index (output channel)
        float4 bb = *(const float4*)(b_e + cglob);
        float s = 0.0f;
        #pragma unroll
        for (int i = 0; i < 8; i++) {
            float4 w = *(const float4*)&wt_sh[r0 + i][jcol];
            float p0 = fmaxf(acc[i][0] + bb.x, 0.0f);
            float p1 = fmaxf(acc[i][1] + bb.y, 0.0f);
            float p2 = fmaxf(acc[i][2] + bb.z, 0.0f);
            float p3 = fmaxf(acc[i][3] + bb.w, 0.0f);
            s += p0 * w.x + p1 * w.y + p2 * w.z + p3 * w.w;
        }
        // reduce within half-warp (16 lanes share one i-group)
        #pragma unroll
        for (int off = 8; off; off >>= 1)
            s += __shfl_down_sync(0xffffffffu, s, off, 16);
        if ((lane & 15) == 0) atomicAdd(&aggs[ig], s);
        __syncthreads();   // protects W_sh overwrite + aggs
    }

    // ---- GRU tail (per-row independent; this block IS row b*64+inode) ----
    // step 1: h=0  ->  xk1 = xrow @ K + bias0 ; hk1 = bias1
    if (t < 192) {
        float s = gbias[t];
        #pragma unroll 8
        for (int k = 0; k < 64; k++) s = fmaf(xrow[k], Kmat[k * 192 + t], s);
        xk1[t] = s;
    }
    __syncthreads();
    if (t < 64) {
        float bz = gbias[192 + t];
        float br = gbias[192 + 64 + t];
        float bh = gbias[192 + 128 + t];
        float z  = 1.0f / (1.0f + expf(-(xk1[t] + bz)));
        float r  = 1.0f / (1.0f + expf(-(xk1[64 + t] + br)));
        float hh = tanhf(xk1[128 + t] + r * bh);
        h1[t] = (1.0f - z) * hh;          // z*h(=0) + (1-z)*hh
    }
    __syncthreads();
    // step 2: x = agg
    if (t < 192) {
        float s1 = gbias[t];
        float s2 = gbias[192 + t];
        #pragma unroll 8
        for (int k = 0; k < 64; k++) {
            s1 = fmaf(aggs[k], Kmat[k * 192 + t], s1);
            s2 = fmaf(h1[k],   Rmat[k * 192 + t], s2);
        }
        xk2[t] = s1; hk2[t] = s2;
    }
    __syncthreads();
    if (t < 64) {
        float z  = 1.0f / (1.0f + expf(-(xk2[t] + hk2[t])));
        float r  = 1.0f / (1.0f + expf(-(xk2[64 + t] + hk2[64 + t])));
        float hh = tanhf(xk2[128 + t] + r * hk2[128 + t]);
        out[((size_t)b * 64 + inode) * 64 + t] = z * h1[t] + (1.0f - z) * hh;
    }
}

extern "C" void kernel_launch(void* const* d_in, const int* in_sizes, int n_in,
                              void* d_out, int out_size) {
    const float* nodes = (const float*)d_in[0];
    const float* edges = (const float*)d_in[1];
    const float* mask  = (const float*)d_in[2];
    const float* W_e   = (const float*)d_in[3];
    const float* b_e   = (const float*)d_in[4];
    const float* gk    = (const float*)d_in[5];
    const float* gr    = (const float*)d_in[6];
    const float* gb    = (const float*)d_in[7];
    float* out = (float*)d_out;

    mp_fused_kernel<<<512, 256>>>(nodes, edges, mask, W_e, b_e, gk, gr, gb, out);
}